// round 17
// baseline (speedup 1.0000x reference)
#include <cuda_runtime.h>
#include <cuda_bf16.h>
#include <cuda_fp16.h>
#include <cstdint>

#define D_MODEL  1024
#define N_HEADS  16
#define HEAD_DIM 64
#define BATCH    2
#define SEQ      2048
#define M_TOT    (BATCH * SEQ)   // 4096
#define WSZ      (D_MODEL * D_MODEL)

// ---------------- scratch (fp16 bits in bf16 containers) ----------------
__device__ __align__(1024) __nv_bfloat16 g_q16[M_TOT * D_MODEL];
__device__ __align__(1024) __nv_bfloat16 g_k16[M_TOT * D_MODEL];
__device__ __align__(1024) __nv_bfloat16 g_v16[M_TOT * D_MODEL];
__device__ __align__(1024) __nv_bfloat16 g_y16[M_TOT * D_MODEL];
__device__ __align__(1024) __nv_bfloat16 g_x16[M_TOT * D_MODEL];
__device__ __align__(1024) __nv_bfloat16 g_w256[4u * WSZ];

// ---------------- helpers ----------------
__device__ __forceinline__ uint32_t smem_u32(const void* p) {
    uint32_t a;
    asm("{ .reg .u64 t; cvta.to.shared.u64 t, %1; cvt.u32.u64 %0, t; }" : "=r"(a) : "l"(p));
    return a;
}
__device__ __forceinline__ uint32_t swz128(uint32_t off) { return off ^ ((off >> 3) & 0x70); }
__device__ __forceinline__ void cp16(uint32_t s, const void* g) {
    asm volatile("cp.async.cg.shared.global [%0], [%1], 16;" :: "r"(s), "l"(g));
}
#define CP_COMMIT() asm volatile("cp.async.commit_group;" ::: "memory")
#define CP_WAIT(n)  asm volatile("cp.async.wait_group %0;" :: "n"(n) : "memory")

__device__ __forceinline__ void ldsm4(uint32_t r[4], uint32_t addr) {
    asm volatile("ldmatrix.sync.aligned.m8n8.x4.shared.b16 {%0,%1,%2,%3}, [%4];"
                 : "=r"(r[0]), "=r"(r[1]), "=r"(r[2]), "=r"(r[3]) : "r"(addr));
}
__device__ __forceinline__ void ldsm4t(uint32_t r[4], uint32_t addr) {
    asm volatile("ldmatrix.sync.aligned.m8n8.x4.trans.shared.b16 {%0,%1,%2,%3}, [%4];"
                 : "=r"(r[0]), "=r"(r[1]), "=r"(r[2]), "=r"(r[3]) : "r"(addr));
}
__device__ __forceinline__ void mma_f16(float d[4], const uint32_t a[4],
                                        uint32_t b0, uint32_t b1) {
    asm volatile(
        "mma.sync.aligned.m16n8k16.row.col.f32.f16.f16.f32 "
        "{%0,%1,%2,%3}, {%4,%5,%6,%7}, {%8,%9}, {%0,%1,%2,%3};"
        : "+f"(d[0]), "+f"(d[1]), "+f"(d[2]), "+f"(d[3])
        : "r"(a[0]), "r"(a[1]), "r"(a[2]), "r"(a[3]), "r"(b0), "r"(b1));
}
__device__ __forceinline__ uint32_t pack_f16x2(float v0, float v1) {
    __half2 h = __floats2half2_rn(v0, v1);
    return *reinterpret_cast<uint32_t*>(&h);
}

// ---------------- fused split: x*16 + weights*256, single fp16 ----------------
#define XN4 (M_TOT * D_MODEL / 4)
#define WN4 (WSZ / 4)

__global__ __launch_bounds__(256) void split_all(
    const float4* __restrict__ x,
    const float4* __restrict__ wq, const float4* __restrict__ wk,
    const float4* __restrict__ wv, const float4* __restrict__ wp,
    uint32_t* __restrict__ x16, uint32_t* __restrict__ w256)
{
    int i = blockIdx.x * 256 + threadIdx.x;
    if (i < XN4) {
        float4 v = x[i];
        x16[2 * i + 0] = pack_f16x2(v.x * 16.0f, v.y * 16.0f);
        x16[2 * i + 1] = pack_f16x2(v.z * 16.0f, v.w * 16.0f);
        return;
    }
    int j = i - XN4;
    int w = j >> 18;
    int off = j & (WN4 - 1);
    const float4* src = (w == 0) ? wq : (w == 1) ? wk : (w == 2) ? wv : wp;
    uint32_t* dst = w256 + (size_t)w * (WSZ / 2);
    float4 v = src[off];
    dst[2 * off + 0] = pack_f16x2(v.x * 256.0f, v.y * 256.0f);
    dst[2 * off + 1] = pack_f16x2(v.z * 256.0f, v.w * 256.0f);
}

// ---------------- HMMA fp16 1-product GEMM (BK=64, SW128, 3-stage) ----------------
// C = (16A)*(256W) * 2^-12 + bias ; fragment loads pipelined one ks ahead.
// MODE 1 (QKV): outputs fp16 of 16*C. MODE 2 (out-proj): fp32 C.
#define T_B    16384
#define NSTG   3
#define STG    (2 * T_B)
#define GEMM_SMEM (NSTG * STG)        // 98304 -> 2 CTAs/SM
#define KCHUNKS (D_MODEL / 64)        // 16

__device__ __forceinline__ void load_stage2(
    uint32_t sbase, const __nv_bfloat16* a0, const __nv_bfloat16* b0,
    int kc, int tid)
{
    const __nv_bfloat16* gs[2] = {a0, b0};
    #pragma unroll
    for (int t = 0; t < 2; t++) {
        uint32_t tb = sbase + t * T_B;
        const __nv_bfloat16* g = gs[t] + kc * 64;
        #pragma unroll
        for (int i = 0; i < 4; i++) {
            int u = i * 256 + tid;
            int r = u >> 3, c8 = u & 7;
            cp16(tb + swz128(r * 128 + c8 * 16), g + (size_t)r * D_MODEL + c8 * 8);
        }
    }
}

template <int MODE>
__global__ __launch_bounds__(256, 2) void gemm_hmma(
    const __nv_bfloat16* __restrict__ A16,
    const __nv_bfloat16* __restrict__ W256,
    const float* __restrict__ biasQ, const float* __restrict__ biasK,
    const float* __restrict__ biasV,
    float* __restrict__ C,
    __nv_bfloat16* __restrict__ Q16, __nv_bfloat16* __restrict__ K16,
    __nv_bfloat16* __restrict__ V16)
{
    extern __shared__ __align__(1024) char smem[];
    const uint32_t sb = smem_u32(smem);
    const int tid = threadIdx.x;
    const int wid = tid >> 5, lane = tid & 31;
    const int which = blockIdx.x >> 3;
    const int n0 = (blockIdx.x & 7) * 128;
    const int m0 = blockIdx.y * 128;
    const int wm = (wid >> 1) * 32;
    const int wn = (wid & 1) * 64;
    const int gid = lane >> 2, tig = lane & 3;

    const float* bias = (which == 0) ? biasQ : (which == 1) ? biasK : biasV;
    __nv_bfloat16* Cout = (which == 0) ? Q16 : (which == 1) ? K16 : V16;

    const __nv_bfloat16* a0 = A16 + (size_t)m0 * D_MODEL;
    const __nv_bfloat16* b0 = W256 + (size_t)which * WSZ + (size_t)n0 * D_MODEL;

    const int a_row  = wm + (lane & 15);
    const int a_byte = ((lane >> 4) & 1) * 16;
    const int b_row  = wn + ((lane >> 4) & 1) * 8 + (lane & 7);
    const int b_byte = ((lane >> 3) & 1) * 16;

    float d[2][8][4];
    #pragma unroll
    for (int i = 0; i < 2; i++)
        #pragma unroll
        for (int j = 0; j < 8; j++)
            #pragma unroll
            for (int c = 0; c < 4; c++) d[i][j][c] = 0.0f;

    load_stage2(sb + 0 * STG, a0, b0, 0, tid);
    CP_COMMIT();
    load_stage2(sb + 1 * STG, a0, b0, 1, tid);
    CP_COMMIT();

    // fragment double buffers (pipelined one ks ahead)
    uint32_t ah[2][2][4];      // [buf][am][4]
    uint32_t bh[2][4][4];      // [buf][pr][4]  (pr covers 2 bn tiles)

    for (int kc = 0; kc < KCHUNKS; kc++) {
        if (kc + 1 < KCHUNKS) { CP_WAIT(1); } else { CP_WAIT(0); }
        __syncthreads();
        if (kc + 2 < KCHUNKS) {
            load_stage2(sb + ((kc + 2) % NSTG) * STG, a0, b0, kc + 2, tid);
            CP_COMMIT();
        }
        const uint32_t st = sb + (kc % NSTG) * STG;

        // preload ks = 0 fragments
        #pragma unroll
        for (int am = 0; am < 2; am++)
            ldsm4(ah[0][am], st + swz128((uint32_t)(a_row + am * 16) * 128 + a_byte));
        #pragma unroll
        for (int pr = 0; pr < 4; pr++)
            ldsm4(bh[0][pr], st + T_B + swz128((uint32_t)(b_row + pr * 16) * 128 + b_byte));

        #pragma unroll
        for (int ks = 0; ks < 4; ks++) {
            const int cur = ks & 1, nxt = cur ^ 1;
            if (ks < 3) {   // prefetch ks+1 fragments before current MMAs
                #pragma unroll
                for (int am = 0; am < 2; am++)
                    ldsm4(ah[nxt][am],
                          st + swz128((uint32_t)(a_row + am * 16) * 128 + a_byte + (ks + 1) * 32));
                #pragma unroll
                for (int pr = 0; pr < 4; pr++)
                    ldsm4(bh[nxt][pr],
                          st + T_B + swz128((uint32_t)(b_row + pr * 16) * 128 + b_byte + (ks + 1) * 32));
            }
            #pragma unroll
            for (int am = 0; am < 2; am++)
                #pragma unroll
                for (int pr = 0; pr < 4; pr++) {
                    mma_f16(d[am][2 * pr],     ah[cur][am], bh[cur][pr][0], bh[cur][pr][1]);
                    mma_f16(d[am][2 * pr + 1], ah[cur][am], bh[cur][pr][2], bh[cur][pr][3]);
                }
        }
    }

    const float osc = 1.0f / 4096.0f;
    #pragma unroll
    for (int am = 0; am < 2; am++) {
        const int row = m0 + wm + am * 16 + gid;
        #pragma unroll
        for (int bn = 0; bn < 8; bn++) {
            const int col = n0 + wn + bn * 8 + tig * 2;
            const float2 bv = *(const float2*)&bias[col];
            float v0 = d[am][bn][0] * osc + bv.x, v1 = d[am][bn][1] * osc + bv.y;
            float v2 = d[am][bn][2] * osc + bv.x, v3 = d[am][bn][3] * osc + bv.y;
            if (MODE == 1) {
                *(uint32_t*)&Cout[(size_t)row * D_MODEL + col] =
                    pack_f16x2(v0 * 16.0f, v1 * 16.0f);
                *(uint32_t*)&Cout[(size_t)(row + 8) * D_MODEL + col] =
                    pack_f16x2(v2 * 16.0f, v3 * 16.0f);
            } else {
                *(float2*)&C[(size_t)row * D_MODEL + col] = make_float2(v0, v1);
                *(float2*)&C[(size_t)(row + 8) * D_MODEL + col] = make_float2(v2, v3);
            }
        }
    }
}

// ---------------- HMMA flash attention (fp16 single, LPT, 2-stage, 2 CTAs/SM) ----------------
#define AQ 128
#define KV_STG 16384
#define ATT_SMEM (AQ * 128 + 2 * KV_STG)   // 49152

__global__ __launch_bounds__(256, 2) void attn_hmma(
    const __nv_bfloat16* __restrict__ Q16,
    const __nv_bfloat16* __restrict__ K16,
    const __nv_bfloat16* __restrict__ V16,
    __nv_bfloat16* __restrict__ Y16)
{
    extern __shared__ __align__(1024) char smA[];
    const uint32_t sb = smem_u32(smA);
    const int tid = threadIdx.x, wid = tid >> 5, lane = tid & 31;
    const int gid = lane >> 2, tig = lane & 3;
    const int qblk = gridDim.y - 1 - blockIdx.y;   // LPT
    const int bh = blockIdx.x;
    const int b = bh >> 4, h = bh & 15;
    const size_t base = ((size_t)b * SEQ) * D_MODEL + (size_t)h * HEAD_DIM;

    const uint32_t sQ = sb;
    const uint32_t sKV = sb + AQ * 128;

    {
        const __nv_bfloat16* q0 = Q16 + base + (size_t)qblk * AQ * D_MODEL;
        #pragma unroll
        for (int i = 0; i < 4; i++) {
            int u = i * 256 + tid;
            int r = u >> 3, c = u & 7;
            cp16(sQ + swz128(r * 128 + c * 16), q0 + (size_t)r * D_MODEL + c * 8);
        }
    }
    CP_COMMIT();

    const int nkt = 2 * qblk + 2;

    {
        const __nv_bfloat16* srcs[2] = {K16 + base, V16 + base};
        #pragma unroll
        for (int t = 0; t < 2; t++)
            #pragma unroll
            for (int i = 0; i < 2; i++) {
                int u = i * 256 + tid;
                int r = u >> 3, c = u & 7;
                cp16(sKV + t * 8192 + swz128(r * 128 + c * 16),
                     srcs[t] + (size_t)r * D_MODEL + c * 8);
            }
    }
    CP_COMMIT();
    CP_WAIT(1);
    __syncthreads();

    uint32_t qf[4][4];
    {
        const int ar = wid * 16 + (lane & 15);
        const int ab = ((lane >> 4) & 1) * 16;
        #pragma unroll
        for (int ks = 0; ks < 4; ks++)
            ldsm4(qf[ks], sQ + swz128((uint32_t)ar * 128 + ab + ks * 32));
    }

    float o[8][4];
    #pragma unroll
    for (int nt = 0; nt < 8; nt++)
        #pragma unroll
        for (int j = 0; j < 4; j++) o[nt][j] = 0.0f;
    float m0 = -1e30f, m1 = -1e30f, l0 = 0.0f, l1 = 0.0f;

    const int qr0 = qblk * AQ + wid * 16 + gid;
    const int row_min = qblk * AQ + wid * 16;
    const int row_max = row_min + 15;

    const int sbr = ((lane >> 4) & 1) * 8 + (lane & 7);
    const int sbb = ((lane >> 3) & 1) * 16;
    const int vrr = lane & 15;
    const int vbb = ((lane >> 4) & 1) * 16;

    const float SC = 0.125f * 1.44269504f / 256.0f;

    for (int kt = 0; kt < nkt; kt++) {
        const uint32_t st = sKV + (uint32_t)(kt & 1) * KV_STG;
        __syncthreads();
        if (kt + 1 < nkt) {
            const size_t koff = base + (size_t)(kt + 1) * 64 * D_MODEL;
            const __nv_bfloat16* srcs[2] = {K16 + koff, V16 + koff};
            const uint32_t dst = sKV + (uint32_t)((kt + 1) & 1) * KV_STG;
            #pragma unroll
            for (int t = 0; t < 2; t++)
                #pragma unroll
                for (int i = 0; i < 2; i++) {
                    int u = i * 256 + tid;
                    int r = u >> 3, c = u & 7;
                    cp16(dst + t * 8192 + swz128(r * 128 + c * 16),
                         srcs[t] + (size_t)r * D_MODEL + c * 8);
                }
            CP_COMMIT();
            CP_WAIT(1);
        } else {
            CP_WAIT(0);
        }
        __syncthreads();

        if (kt * 64 > row_max) continue;

        float s[8][4];
        #pragma unroll
        for (int nt = 0; nt < 8; nt++)
            #pragma unroll
            for (int j = 0; j < 4; j++) s[nt][j] = 0.0f;

        #pragma unroll
        for (int ks = 0; ks < 4; ks++) {
            #pragma unroll
            for (int np = 0; np < 4; np++) {
                uint32_t off = swz128((uint32_t)(np * 16 + sbr) * 128 + sbb + ks * 32);
                uint32_t rk[4];
                ldsm4(rk, st + off);
                mma_f16(s[2 * np],     qf[ks], rk[0], rk[1]);
                mma_f16(s[2 * np + 1], qf[ks], rk[2], rk[3]);
            }
        }

        const bool need_mask = (kt * 64 + 63 > row_min);
        #pragma unroll
        for (int nt = 0; nt < 8; nt++) {
            #pragma unroll
            for (int j = 0; j < 4; j++) s[nt][j] *= SC;
            if (need_mask) {
                const int kc = kt * 64 + nt * 8 + 2 * tig;
                if (kc     > qr0)     s[nt][0] = -1e30f;
                if (kc + 1 > qr0)     s[nt][1] = -1e30f;
                if (kc     > qr0 + 8) s[nt][2] = -1e30f;
                if (kc + 1 > qr0 + 8) s[nt][3] = -1e30f;
            }
        }

        float mx0 = -1e30f, mx1 = -1e30f;
        #pragma unroll
        for (int nt = 0; nt < 8; nt++) {
            mx0 = fmaxf(mx0, fmaxf(s[nt][0], s[nt][1]));
            mx1 = fmaxf(mx1, fmaxf(s[nt][2], s[nt][3]));
        }
        mx0 = fmaxf(mx0, __shfl_xor_sync(0xffffffffu, mx0, 1));
        mx0 = fmaxf(mx0, __shfl_xor_sync(0xffffffffu, mx0, 2));
        mx1 = fmaxf(mx1, __shfl_xor_sync(0xffffffffu, mx1, 1));
        mx1 = fmaxf(mx1, __shfl_xor_sync(0xffffffffu, mx1, 2));
        const float nm0 = fmaxf(m0, mx0), nm1 = fmaxf(m1, mx1);
        const float c0 = exp2f(m0 - nm0), c1 = exp2f(m1 - nm1);
        m0 = nm0; m1 = nm1;

        uint32_t pA[8], pB[8];
        float la0 = 0.0f, la1 = 0.0f;
        #pragma unroll
        for (int nt = 0; nt < 8; nt++) {
            float p0 = exp2f(s[nt][0] - m0), p1 = exp2f(s[nt][1] - m0);
            float p2 = exp2f(s[nt][2] - m1), p3 = exp2f(s[nt][3] - m1);
            la0 += p0 + p1; la1 += p2 + p3;
            pA[nt] = pack_f16x2(p0, p1);
            pB[nt] = pack_f16x2(p2, p3);
        }
        la0 += __shfl_xor_sync(0xffffffffu, la0, 1);
        la0 += __shfl_xor_sync(0xffffffffu, la0, 2);
        la1 += __shfl_xor_sync(0xffffffffu, la1, 1);
        la1 += __shfl_xor_sync(0xffffffffu, la1, 2);
        l0 = l0 * c0 + la0;
        l1 = l1 * c1 + la1;
        #pragma unroll
        for (int nt = 0; nt < 8; nt++) {
            o[nt][0] *= c0; o[nt][1] *= c0;
            o[nt][2] *= c1; o[nt][3] *= c1;
        }

        #pragma unroll
        for (int kk = 0; kk < 4; kk++) {
            uint32_t aH[4] = {pA[2 * kk], pB[2 * kk], pA[2 * kk + 1], pB[2 * kk + 1]};
            #pragma unroll
            for (int np = 0; np < 4; np++) {
                uint32_t off = swz128((uint32_t)(kk * 16 + vrr) * 128 + vbb + np * 32);
                uint32_t rv[4];
                ldsm4t(rv, st + 8192 + off);
                mma_f16(o[2 * np],     aH, rv[0], rv[1]);
                mma_f16(o[2 * np + 1], aH, rv[2], rv[3]);
            }
        }
    }

    const float i0 = 1.0f / l0, i1 = 1.0f / l1;
    const size_t r0a = base + (size_t)qr0 * D_MODEL;
    const size_t r1a = base + (size_t)(qr0 + 8) * D_MODEL;
    #pragma unroll
    for (int nt = 0; nt < 8; nt++) {
        const int col = nt * 8 + 2 * tig;
        *(uint32_t*)&Y16[r0a + col] = pack_f16x2(o[nt][0] * i0, o[nt][1] * i0);
        *(uint32_t*)&Y16[r1a + col] = pack_f16x2(o[nt][2] * i1, o[nt][3] * i1);
    }
}

// ---------------- launch ----------------
extern "C" void kernel_launch(void* const* d_in, const int* in_sizes, int n_in,
                              void* d_out, int out_size)
{
    const float* x  = (const float*)d_in[0];
    const float* Wq = (const float*)d_in[1];
    const float* bq = (const float*)d_in[2];
    const float* Wk = (const float*)d_in[3];
    const float* bk = (const float*)d_in[4];
    const float* Wv = (const float*)d_in[5];
    const float* bv = (const float*)d_in[6];
    const float* Wp = (const float*)d_in[7];
    const float* bp = (const float*)d_in[8];
    float* out = (float*)d_out;

    __nv_bfloat16 *q16, *k16, *v16, *y16, *x16, *w256;
    cudaGetSymbolAddress((void**)&q16, g_q16);
    cudaGetSymbolAddress((void**)&k16, g_k16);
    cudaGetSymbolAddress((void**)&v16, g_v16);
    cudaGetSymbolAddress((void**)&y16, g_y16);
    cudaGetSymbolAddress((void**)&x16, g_x16);
    cudaGetSymbolAddress((void**)&w256, g_w256);

    cudaFuncSetAttribute(gemm_hmma<1>,
                         cudaFuncAttributeMaxDynamicSharedMemorySize, GEMM_SMEM);
    cudaFuncSetAttribute(gemm_hmma<2>,
                         cudaFuncAttributeMaxDynamicSharedMemorySize, GEMM_SMEM);
    cudaFuncSetAttribute(attn_hmma,
                         cudaFuncAttributeMaxDynamicSharedMemorySize, ATT_SMEM);

    split_all<<<(XN4 + 4 * WN4) / 256, 256>>>(
        (const float4*)x, (const float4*)Wq, (const float4*)Wk,
        (const float4*)Wv, (const float4*)Wp,
        (uint32_t*)x16, (uint32_t*)w256);

    gemm_hmma<1><<<dim3(24, 32), 256, GEMM_SMEM>>>(
        x16, w256, bq, bk, bv,
        nullptr, q16, k16, v16);

    attn_hmma<<<dim3(BATCH * N_HEADS, SEQ / AQ), 256, ATT_SMEM>>>(
        q16, k16, v16, y16);

    gemm_hmma<2><<<dim3(8, 32), 256, GEMM_SMEM>>>(
        y16, w256 + 3u * WSZ, bp, nullptr, nullptr,
        out, nullptr, nullptr, nullptr);
}